// round 12
// baseline (speedup 1.0000x reference)
#include <cuda_runtime.h>
#include <cuda_bf16.h>
#include <cuda_fp16.h>
#include <cstdint>

#define MAX_N 100000
#define MAX_E 1600000
#define D 128
#define NB_MAX 128

// Scratch (device globals -- no allocation allowed)
__device__ __half g_hh[(size_t)MAX_N * D];     // 25.6 MB fp16 h
__device__ float g_si[MAX_N];
__device__ float g_sj[MAX_N];
__device__ int   g_cnt[MAX_N];                 // edge hist; countdown restores to 0
__device__ int   g_offp[MAX_N];                // block-local exclusive prefix
__device__ int   g_bsum[NB_MAX];
__device__ int   g_bpre[NB_MAX];
__device__ int   g_d[MAX_E];                   // dst sorted by src (edges only)

__device__ __forceinline__ unsigned h2_to_u32(__half2 h) {
    unsigned u; *reinterpret_cast<__half2*>(&u) = h; return u;
}
__device__ __forceinline__ __half2 u32_to_h2(unsigned u) {
    return *reinterpret_cast<__half2*>(&u);
}

// ---------------------------------------------------------------------------
// Tensor-core GEMM: h = x @ W^T + b via mma.sync m16n8k16 f16f16f32.
// Block tile 128x128, K chunked 2x64. 8 warps: 4 in M x 2 in N.
// (round-7 proven configuration)
// ---------------------------------------------------------------------------
#define KC 64
#define XPITCH 72              // smem row pitch in halves (64 + 8 pad)
#define HPITCH 136             // epilogue pitch (128 + 8 pad)

__global__ __launch_bounds__(256, 2)
void gemm_kernel(const float* __restrict__ x, const float* __restrict__ W,
                 const float* __restrict__ b, const float* __restrict__ Watt,
                 int n) {
    __shared__ __align__(16) char smem_raw[2 * 128 * XPITCH * 2]; // 36864 B
    __half (*xs)[XPITCH] = (__half(*)[XPITCH])smem_raw;
    __half (*ws)[XPITCH] = (__half(*)[XPITCH])(smem_raw + 128 * XPITCH * 2);
    __half (*hs)[HPITCH] = (__half(*)[HPITCH])smem_raw;   // epilogue reuse

    int tid = threadIdx.x;
    int wid = tid >> 5;
    int lane = tid & 31;
    int gid = lane >> 2;
    int tig = lane & 3;
    int wm = wid & 3;
    int wn = wid >> 2;
    int row0 = blockIdx.x * 128;

    float c[2][8][4];
#pragma unroll
    for (int mi = 0; mi < 2; mi++)
#pragma unroll
        for (int ni = 0; ni < 8; ni++)
#pragma unroll
            for (int r = 0; r < 4; r++) c[mi][ni][r] = 0.f;

#pragma unroll
    for (int kk = 0; kk < D; kk += KC) {
#pragma unroll
        for (int r = 0; r < 8; r++) {
            int idx = tid + r * 256;
            int row = idx >> 4;
            int c4 = (idx & 15) * 4;
            float4 v = make_float4(0.f, 0.f, 0.f, 0.f);
            int gr = row0 + row;
            if (gr < n) v = *(const float4*)&x[(size_t)gr * D + kk + c4];
            unsigned p0 = h2_to_u32(__floats2half2_rn(v.x, v.y));
            unsigned p1 = h2_to_u32(__floats2half2_rn(v.z, v.w));
            *(uint2*)&xs[row][c4] = make_uint2(p0, p1);
        }
#pragma unroll
        for (int r = 0; r < 8; r++) {
            int idx = tid + r * 256;
            int cc = idx >> 4;
            int c4 = (idx & 15) * 4;
            float4 v = *(const float4*)&W[(size_t)cc * D + kk + c4];
            unsigned p0 = h2_to_u32(__floats2half2_rn(v.x, v.y));
            unsigned p1 = h2_to_u32(__floats2half2_rn(v.z, v.w));
            *(uint2*)&ws[cc][c4] = make_uint2(p0, p1);
        }
        __syncthreads();

#pragma unroll
        for (int ks = 0; ks < KC / 16; ks++) {
            int kb = ks * 16 + tig * 2;
            unsigned a[2][4];
#pragma unroll
            for (int mi = 0; mi < 2; mi++) {
                int ra = wm * 32 + mi * 16 + gid;
                a[mi][0] = *(const unsigned*)&xs[ra][kb];
                a[mi][1] = *(const unsigned*)&xs[ra + 8][kb];
                a[mi][2] = *(const unsigned*)&xs[ra][kb + 8];
                a[mi][3] = *(const unsigned*)&xs[ra + 8][kb + 8];
            }
#pragma unroll
            for (int ni = 0; ni < 8; ni++) {
                int cb = wn * 64 + ni * 8 + gid;
                unsigned b0 = *(const unsigned*)&ws[cb][kb];
                unsigned b1 = *(const unsigned*)&ws[cb][kb + 8];
#pragma unroll
                for (int mi = 0; mi < 2; mi++) {
                    asm volatile(
                        "mma.sync.aligned.m16n8k16.row.col.f32.f16.f16.f32 "
                        "{%0,%1,%2,%3}, {%4,%5,%6,%7}, {%8,%9}, {%0,%1,%2,%3};"
                        : "+f"(c[mi][ni][0]), "+f"(c[mi][ni][1]),
                          "+f"(c[mi][ni][2]), "+f"(c[mi][ni][3])
                        : "r"(a[mi][0]), "r"(a[mi][1]), "r"(a[mi][2]), "r"(a[mi][3]),
                          "r"(b0), "r"(b1));
                }
            }
        }
        __syncthreads();
    }

    // epilogue pass 1: +bias, fp16, stage in smem
#pragma unroll
    for (int mi = 0; mi < 2; mi++) {
#pragma unroll
        for (int ni = 0; ni < 8; ni++) {
            int rr = wm * 32 + mi * 16 + gid;
            int col = wn * 64 + ni * 8 + tig * 2;
            float bx = __ldg(&b[col]);
            float by = __ldg(&b[col + 1]);
            *(unsigned*)&hs[rr][col] =
                h2_to_u32(__floats2half2_rn(c[mi][ni][0] + bx, c[mi][ni][1] + by));
            *(unsigned*)&hs[rr + 8][col] =
                h2_to_u32(__floats2half2_rn(c[mi][ni][2] + bx, c[mi][ni][3] + by));
        }
    }
    __syncthreads();

    // epilogue pass 2: coalesced store + fused s_i/s_j
    int tx = tid & 15;
    int tyr = tid >> 4;
    float ai_r[8], aj_r[8];
#pragma unroll
    for (int j = 0; j < 8; j++) {
        ai_r[j] = __ldg(&Watt[tx * 8 + j]);
        aj_r[j] = __ldg(&Watt[D + tx * 8 + j]);
    }
#pragma unroll
    for (int it = 0; it < 8; it++) {
        int row = it * 16 + tyr;
        int gr = row0 + row;
        uint4 v = *(const uint4*)&hs[row][tx * 8];
        float2 f0 = __half22float2(u32_to_h2(v.x));
        float2 f1 = __half22float2(u32_to_h2(v.y));
        float2 f2 = __half22float2(u32_to_h2(v.z));
        float2 f3 = __half22float2(u32_to_h2(v.w));
        float psi = f0.x*ai_r[0] + f0.y*ai_r[1] + f1.x*ai_r[2] + f1.y*ai_r[3]
                  + f2.x*ai_r[4] + f2.y*ai_r[5] + f3.x*ai_r[6] + f3.y*ai_r[7];
        float psj = f0.x*aj_r[0] + f0.y*aj_r[1] + f1.x*aj_r[2] + f1.y*aj_r[3]
                  + f2.x*aj_r[4] + f2.y*aj_r[5] + f3.x*aj_r[6] + f3.y*aj_r[7];
#pragma unroll
        for (int o = 8; o; o >>= 1) {
            psi += __shfl_down_sync(0xffffffffu, psi, o, 16);
            psj += __shfl_down_sync(0xffffffffu, psj, o, 16);
        }
        if (gr < n) {
            *(uint4*)&g_hh[(size_t)gr * D + tx * 8] = v;
            if (tx == 0) { g_si[gr] = psi; g_sj[gr] = psj; }
        }
    }
}

// ---------------------------------------------------------------------------
// hist: 4 edges per thread (ILP for atomic latency)
// ---------------------------------------------------------------------------
__global__ void hist_kernel(const int* __restrict__ ei, int E) {
    int t4 = (blockIdx.x * blockDim.x + threadIdx.x) * 4;
    if (t4 + 3 < E) {
        int4 s4 = *(const int4*)&ei[t4];
        atomicAdd(&g_cnt[s4.x], 1);
        atomicAdd(&g_cnt[s4.y], 1);
        atomicAdd(&g_cnt[s4.z], 1);
        atomicAdd(&g_cnt[s4.w], 1);
    } else {
        for (int t = t4; t < E; t++) atomicAdd(&g_cnt[ei[t]], 1);
    }
}

// ---------------------------------------------------------------------------
// exclusive scan over edge counts (self-loops NOT included in slots)
// ---------------------------------------------------------------------------
__global__ void scan1_kernel(int n) {
    __shared__ int sh[1024];
    int i = blockIdx.x * 1024 + threadIdx.x;
    int v = (i < n) ? g_cnt[i] : 0;
    sh[threadIdx.x] = v;
    __syncthreads();
    for (int off = 1; off < 1024; off <<= 1) {
        int t = (threadIdx.x >= off) ? sh[threadIdx.x - off] : 0;
        __syncthreads();
        sh[threadIdx.x] += t;
        __syncthreads();
    }
    if (i < n) g_offp[i] = sh[threadIdx.x] - v;
    if (threadIdx.x == 1023) g_bsum[blockIdx.x] = sh[1023];
}

__global__ void scan2_kernel(int nb) {
    __shared__ int sh[NB_MAX];
    int t = threadIdx.x;
    int v = (t < nb) ? g_bsum[t] : 0;
    sh[t] = v;
    __syncthreads();
    for (int off = 1; off < NB_MAX; off <<= 1) {
        int u = (t >= off) ? sh[t - off] : 0;
        __syncthreads();
        sh[t] += u;
        __syncthreads();
    }
    if (t < nb) g_bpre[t] = sh[t] - v;
}

// ---------------------------------------------------------------------------
// sort: counting-sort scatter of dst by src, 4 edges per thread (ILP).
// g_cnt counts down to 0 (replay-safe). Score-free -> overlaps the GEMM.
// ---------------------------------------------------------------------------
__global__ void sort_kernel(const int* __restrict__ ei, int E) {
    int t4 = (blockIdx.x * blockDim.x + threadIdx.x) * 4;
    if (t4 + 3 < E) {
        int4 s4 = *(const int4*)&ei[t4];
        int4 d4 = *(const int4*)&ei[E + t4];
        int o0 = atomicAdd(&g_cnt[s4.x], -1);
        int o1 = atomicAdd(&g_cnt[s4.y], -1);
        int o2 = atomicAdd(&g_cnt[s4.z], -1);
        int o3 = atomicAdd(&g_cnt[s4.w], -1);
        g_d[g_offp[s4.x] + g_bpre[s4.x >> 10] + o0 - 1] = d4.x;
        g_d[g_offp[s4.y] + g_bpre[s4.y >> 10] + o1 - 1] = d4.y;
        g_d[g_offp[s4.z] + g_bpre[s4.z >> 10] + o2 - 1] = d4.z;
        g_d[g_offp[s4.w] + g_bpre[s4.w >> 10] + o3 - 1] = d4.w;
    } else {
        for (int t = t4; t < E; t++) {
            int src = ei[t];
            int dst = ei[E + t];
            int old = atomicAdd(&g_cnt[src], -1);
            g_d[g_offp[src] + g_bpre[src >> 10] + old - 1] = dst;
        }
    }
}

// ---------------------------------------------------------------------------
// aggregation: warp per src node, TWO 16-lane groups each handling one edge.
// Per edge: broadcast d + sj (half-warp uniform loads), redundant expf,
// 16B/lane row gather (16 lanes = 256B row). No per-edge shuffles; groups
// combined once at the end with shfl_xor(16). Fused normalize + ELU.
// ---------------------------------------------------------------------------
__global__ __launch_bounds__(256)
void aggregate_kernel(float* __restrict__ out, const float* __restrict__ batt,
                      int n, int E) {
    int w = (blockIdx.x * blockDim.x + threadIdx.x) >> 5;
    int lane = threadIdx.x & 31;
    if (w >= n) return;
    int g = lane >> 4;          // edge-slot within pair
    int li = lane & 15;         // covers cols [8*li, 8*li+8)
    int s = g_offp[w] + g_bpre[w >> 10];
    int e = (w + 1 < n) ? (g_offp[w + 1] + g_bpre[(w + 1) >> 10]) : E;

    float bb = __ldg(batt);
    float si_w = g_si[w];

    // self loop term (counted once: group 0 only)
    float scs = si_w + g_sj[w] + bb;
    scs = (scs >= 0.f) ? scs : 0.01f * scs;
    float es = expf(scs);

    float acc[8];
    {
        uint4 r = *(const uint4*)&g_hh[(size_t)w * D + li * 8];
        float2 f0 = __half22float2(u32_to_h2(r.x));
        float2 f1 = __half22float2(u32_to_h2(r.y));
        float2 f2 = __half22float2(u32_to_h2(r.z));
        float2 f3 = __half22float2(u32_to_h2(r.w));
        float e0 = (g == 0) ? es : 0.f;
        acc[0] = e0 * f0.x; acc[1] = e0 * f0.y;
        acc[2] = e0 * f1.x; acc[3] = e0 * f1.y;
        acc[4] = e0 * f2.x; acc[5] = e0 * f2.y;
        acc[6] = e0 * f3.x; acc[7] = e0 * f3.y;
    }
    float denp = 0.f;

    int k = s;
    // main loop: 4 edges per iteration (2 per group, independent gathers)
    for (; k + 3 < e; k += 4) {
        int i0 = k + g, i1 = k + 2 + g;
        int d0 = g_d[i0];
        int d1 = g_d[i1];
        float sj0 = __ldg(&g_sj[d0]);
        float sj1 = __ldg(&g_sj[d1]);
        uint4 r0 = *(const uint4*)&g_hh[(size_t)d0 * D + li * 8];
        uint4 r1 = *(const uint4*)&g_hh[(size_t)d1 * D + li * 8];
        float sc0 = si_w + sj0 + bb; sc0 = (sc0 >= 0.f) ? sc0 : 0.01f * sc0;
        float sc1 = si_w + sj1 + bb; sc1 = (sc1 >= 0.f) ? sc1 : 0.01f * sc1;
        float e0 = expf(sc0), e1 = expf(sc1);
        if (li == 0) denp += e0 + e1;
        float2 f0 = __half22float2(u32_to_h2(r0.x));
        float2 f1 = __half22float2(u32_to_h2(r0.y));
        float2 f2 = __half22float2(u32_to_h2(r0.z));
        float2 f3 = __half22float2(u32_to_h2(r0.w));
        acc[0] += e0 * f0.x; acc[1] += e0 * f0.y;
        acc[2] += e0 * f1.x; acc[3] += e0 * f1.y;
        acc[4] += e0 * f2.x; acc[5] += e0 * f2.y;
        acc[6] += e0 * f3.x; acc[7] += e0 * f3.y;
        f0 = __half22float2(u32_to_h2(r1.x));
        f1 = __half22float2(u32_to_h2(r1.y));
        f2 = __half22float2(u32_to_h2(r1.z));
        f3 = __half22float2(u32_to_h2(r1.w));
        acc[0] += e1 * f0.x; acc[1] += e1 * f0.y;
        acc[2] += e1 * f1.x; acc[3] += e1 * f1.y;
        acc[4] += e1 * f2.x; acc[5] += e1 * f2.y;
        acc[6] += e1 * f3.x; acc[7] += e1 * f3.y;
    }
    // tail: 2 at a time with guard
    for (; k < e; k += 2) {
        int i0 = k + g;
        bool act = i0 < e;
        int d0 = act ? g_d[i0] : w;
        float e0 = 0.f;
        if (act) {
            float sc = si_w + __ldg(&g_sj[d0]) + bb;
            sc = (sc >= 0.f) ? sc : 0.01f * sc;
            e0 = expf(sc);
        }
        if (li == 0) denp += e0;
        uint4 r0 = *(const uint4*)&g_hh[(size_t)d0 * D + li * 8];
        float2 f0 = __half22float2(u32_to_h2(r0.x));
        float2 f1 = __half22float2(u32_to_h2(r0.y));
        float2 f2 = __half22float2(u32_to_h2(r0.z));
        float2 f3 = __half22float2(u32_to_h2(r0.w));
        acc[0] += e0 * f0.x; acc[1] += e0 * f0.y;
        acc[2] += e0 * f1.x; acc[3] += e0 * f1.y;
        acc[4] += e0 * f2.x; acc[5] += e0 * f2.y;
        acc[6] += e0 * f3.x; acc[7] += e0 * f3.y;
    }

    // combine the two groups (same columns, different edges)
#pragma unroll
    for (int j = 0; j < 8; j++)
        acc[j] += __shfl_xor_sync(0xffffffffu, acc[j], 16);
    float den = denp;
#pragma unroll
    for (int o = 16; o; o >>= 1) den += __shfl_xor_sync(0xffffffffu, den, o);
    den += es;

    float inv = 1.f / den;
    // group 0 writes cols [8li, 8li+4), group 1 writes [8li+4, 8li+8)
    float o0 = acc[4 * g + 0] * inv;
    float o1 = acc[4 * g + 1] * inv;
    float o2 = acc[4 * g + 2] * inv;
    float o3 = acc[4 * g + 3] * inv;
    o0 = (o0 > 0.f) ? o0 : expm1f(o0);
    o1 = (o1 > 0.f) ? o1 : expm1f(o1);
    o2 = (o2 > 0.f) ? o2 : expm1f(o2);
    o3 = (o3 > 0.f) ? o3 : expm1f(o3);
    float* p = &out[(size_t)w * D + li * 8 + 4 * g];
    asm volatile("st.global.cs.v4.f32 [%0], {%1,%2,%3,%4};"
                 :: "l"(p), "f"(o0), "f"(o1), "f"(o2), "f"(o3) : "memory");
}

// ---------------------------------------------------------------------------
extern "C" void kernel_launch(void* const* d_in, const int* in_sizes, int n_in,
                              void* d_out, int out_size) {
    const float* x    = (const float*)d_in[0];
    const int*   ei   = (const int*)  d_in[1];
    const float* W    = (const float*)d_in[2];
    const float* b    = (const float*)d_in[3];
    const float* Watt = (const float*)d_in[4];
    const float* batt = (const float*)d_in[5];
    float* out = (float*)d_out;

    int n = in_sizes[0] / D;
    int E = in_sizes[1] / 2;
    int nb = (n + 1023) / 1024;
    int e4 = (E + 3) / 4;

    // side stream + events for fork/join inside graph capture (created once)
    static cudaStream_t s1 = nullptr;
    static cudaEvent_t ev_fork = nullptr, ev_join = nullptr;
    if (s1 == nullptr) {
        cudaStreamCreateWithFlags(&s1, cudaStreamNonBlocking);
        cudaEventCreateWithFlags(&ev_fork, cudaEventDisableTiming);
        cudaEventCreateWithFlags(&ev_join, cudaEventDisableTiming);
    }

    // fork: FULL edge pipeline (hist -> scans -> sort) concurrent with GEMM
    cudaEventRecord(ev_fork, 0);
    cudaStreamWaitEvent(s1, ev_fork, 0);
    hist_kernel<<<(e4 + 255) / 256, 256, 0, s1>>>(ei, E);
    scan1_kernel<<<nb, 1024, 0, s1>>>(n);
    scan2_kernel<<<1, NB_MAX, 0, s1>>>(nb);
    sort_kernel<<<(e4 + 255) / 256, 256, 0, s1>>>(ei, E);
    cudaEventRecord(ev_join, s1);

    gemm_kernel<<<(n + 127) / 128, 256>>>(x, W, b, Watt, n);

    cudaStreamWaitEvent(0, ev_join, 0);
    aggregate_kernel<<<((long long)n * 32 + 255) / 256, 256>>>(out, batt, n, E);
}